// round 4
// baseline (speedup 1.0000x reference)
#include <cuda_runtime.h>
#include <math.h>

#define HH 512
#define BB 64
#define SS 400
#define VV 50000
#define VS 50400
#define SPL 8

typedef unsigned long long ull;

// ---------------- scratch ----------------
__device__ __align__(16) float g_gip[SPL * 1536 * 64];
__device__ __align__(16) float g_ghp[SPL * 1536 * 64];
__device__ __align__(16) float g_x2p[SPL * 512 * 64];
__device__ __align__(16) float g_x2s[512 * 64];
__device__ __align__(16) float g_h[BB * HH];
__device__ __align__(16) float g_spart[8 * SS * BB];
__device__ __align__(16) float g_attn[SS * BB];
__device__ __align__(16) float g_gs[BB * 2 * HH];
__device__ __align__(16) float g_p[BB];

// ---------------- f32x2 helpers ----------------
__device__ __forceinline__ ull fma2(ull a, ull b, ull c) {
    ull d;
    asm("fma.rn.f32x2 %0, %1, %2, %3;" : "=l"(d) : "l"(a), "l"(b), "l"(c));
    return d;
}
__device__ __forceinline__ float2 unpk(ull v) {
    unsigned lo, hi;
    asm("mov.b64 {%0,%1}, %2;" : "=r"(lo), "=r"(hi) : "l"(v));
    return make_float2(__uint_as_float(lo), __uint_as_float(hi));
}

// ============ big NT GEMM, double-buffered, dup-B smem, m-paired acc ============
// C[m][n] = sum_k A[m][k] * B(n,k). BM=128, BN=64, BK=16, 128 threads.
// TB=false: B row-major [n][k] stride K. TB=true: B is [k][n] stride ldb.
// EPI1: out[by*25600+m] = sum_n tanh(acc + x2s[n][b]) * v[n]   (8 n-block partials)
// EPI2: out[n*VS+m] = p[n] * selu(acc + bias[m])
template <int EPI, bool TB>
__global__ void __launch_bounds__(128)
gemm_nt(const float* __restrict__ A, const float* __restrict__ Bm,
        const float* __restrict__ bias, float* __restrict__ out,
        int M, int K, int ldb,
        const float* __restrict__ x2s, const float* __restrict__ ev,
        const float* __restrict__ ep)
{
    __shared__ float sh[8256];   // buf0[0..4096) buf1[4096..8192) ps[8192..8256)

    const int tid = threadIdx.x;
    const int tmq = tid & 15, tnq = tid >> 4;
    const int mBase = blockIdx.x * 128, nBase = blockIdx.y * 64;

    if (EPI == 2 && tid < 64) sh[8192 + tid] = ep[tid];

    ull acc[4][8];
    #pragma unroll
    for (int i = 0; i < 4; i++)
        #pragma unroll
        for (int j = 0; j < 8; j++) acc[i][j] = 0ull;

    float4 pa[4], pb[2];

    auto loadA = [&](int k0) {
        #pragma unroll
        for (int i = 0; i < 4; i++) {
            int q = tid + 128 * i, r = q >> 2, c4 = q & 3;
            int m = mBase + r;
            pa[i] = (m < M) ? *(const float4*)(A + (size_t)m * K + k0 + c4 * 4)
                            : make_float4(0.f, 0.f, 0.f, 0.f);
        }
    };
    auto loadB = [&](int k0) {
        #pragma unroll
        for (int i = 0; i < 2; i++) {
            int q = tid + 128 * i;
            if (!TB) {
                int r = q >> 2, c4 = q & 3;
                pb[i] = *(const float4*)(Bm + (size_t)r * K + k0 + c4 * 4);
            } else {
                int kk = q >> 4, n4 = q & 15;
                pb[i] = *(const float4*)(Bm + (size_t)(k0 + kk) * ldb + nBase + n4 * 4);
            }
        }
    };
    auto storeT = [&](float* buf) {
        float* sA = buf;            // [16][128]  transposed A
        float* sBd = buf + 2048;    // [16][128]  duplicated B
        #pragma unroll
        for (int i = 0; i < 4; i++) {
            int q = tid + 128 * i, r = q >> 2, c4 = q & 3;
            sA[(c4 * 4 + 0) * 128 + r] = pa[i].x;
            sA[(c4 * 4 + 1) * 128 + r] = pa[i].y;
            sA[(c4 * 4 + 2) * 128 + r] = pa[i].z;
            sA[(c4 * 4 + 3) * 128 + r] = pa[i].w;
        }
        #pragma unroll
        for (int i = 0; i < 2; i++) {
            int q = tid + 128 * i;
            if (!TB) {
                int r = q >> 2, c4 = q & 3;   // r = n, 4 consecutive k
                float vv[4] = {pb[i].x, pb[i].y, pb[i].z, pb[i].w};
                #pragma unroll
                for (int j = 0; j < 4; j++)
                    *(float2*)&sBd[(c4 * 4 + j) * 128 + 2 * r] = make_float2(vv[j], vv[j]);
            } else {
                int kk = q >> 4, n4 = q & 15; // one k, 4 consecutive n
                float vv[4] = {pb[i].x, pb[i].y, pb[i].z, pb[i].w};
                #pragma unroll
                for (int j = 0; j < 4; j++)
                    *(float2*)&sBd[kk * 128 + 2 * (n4 * 4 + j)] = make_float2(vv[j], vv[j]);
            }
        }
    };

    loadA(0); loadB(0);
    storeT(sh);
    __syncthreads();

    const int T = K >> 4;
    for (int t = 0; t < T; t++) {
        float* cb = sh + (t & 1) * 4096;
        if (t + 1 < T) { loadA((t + 1) << 4); loadB((t + 1) << 4); }
        const float* sA = cb;
        const float* sBd = cb + 2048;
        #pragma unroll
        for (int kk = 0; kk < 16; kk++) {
            const ulonglong2 a0 = *(const ulonglong2*)&sA[kk * 128 + tmq * 4];
            const ulonglong2 a1 = *(const ulonglong2*)&sA[kk * 128 + 64 + tmq * 4];
            const ulonglong2 b0 = *(const ulonglong2*)&sBd[kk * 128 + tnq * 8];
            const ulonglong2 b1 = *(const ulonglong2*)&sBd[kk * 128 + tnq * 8 + 4];
            const ulonglong2 b2 = *(const ulonglong2*)&sBd[kk * 128 + 64 + tnq * 8];
            const ulonglong2 b3 = *(const ulonglong2*)&sBd[kk * 128 + 68 + tnq * 8];
            ull av[4] = {a0.x, a0.y, a1.x, a1.y};
            ull bv[8] = {b0.x, b0.y, b1.x, b1.y, b2.x, b2.y, b3.x, b3.y};
            #pragma unroll
            for (int mp = 0; mp < 4; mp++)
                #pragma unroll
                for (int n = 0; n < 8; n++)
                    acc[mp][n] = fma2(av[mp], bv[n], acc[mp][n]);
        }
        if (t + 1 < T) storeT(sh + ((t + 1) & 1) * 4096);
        __syncthreads();
    }

    // m mapping: mp -> base row; acc holds (m, m+1)
    // mp0: tmq*4, mp1: tmq*4+2, mp2: 64+tmq*4, mp3: 64+tmq*4+2
    if (EPI == 1) {
        // overlay (buffers dead): x2 tile [64n][64b] at sh[0..4096), vs at 4096, red at 4224
        {
            const float4* xsrc = (const float4*)(x2s + (size_t)nBase * 64);
            float4* xdst = (float4*)sh;
            #pragma unroll
            for (int i = 0; i < 8; i++) xdst[tid + 128 * i] = xsrc[tid + 128 * i];
            if (tid < 64) sh[4096 + tid] = ev[nBase + tid];
        }
        __syncthreads();
        const float* x2t = sh;
        const float* vs = sh + 4096;
        float* red = sh + 4224;
        float sacc[8] = {0.f, 0.f, 0.f, 0.f, 0.f, 0.f, 0.f, 0.f};
        #pragma unroll
        for (int mp = 0; mp < 4; mp++) {
            int m0 = ((mp & 1) ? tmq * 4 + 2 : tmq * 4) + ((mp >> 1) ? 64 : 0);
            int bc0 = m0 & 63, bc1 = (m0 + 1) & 63;
            #pragma unroll
            for (int n = 0; n < 8; n++) {
                int nn = (n < 4) ? (tnq * 4 + n) : (32 + tnq * 4 + n - 4);
                float2 c = unpk(acc[mp][n]);
                float vn = vs[nn];
                sacc[mp * 2 + 0] += tanhf(c.x + x2t[nn * 64 + bc0]) * vn;
                sacc[mp * 2 + 1] += tanhf(c.y + x2t[nn * 64 + bc1]) * vn;
            }
        }
        #pragma unroll
        for (int mp = 0; mp < 4; mp++) {
            int m0 = ((mp & 1) ? tmq * 4 + 2 : tmq * 4) + ((mp >> 1) ? 64 : 0);
            red[tnq * 128 + m0] = sacc[mp * 2];
            red[tnq * 128 + m0 + 1] = sacc[mp * 2 + 1];
        }
        __syncthreads();
        float tsum = 0.f;
        #pragma unroll
        for (int g = 0; g < 8; g++) tsum += red[g * 128 + tid];
        out[(size_t)blockIdx.y * (SS * BB) + mBase + tid] = tsum;
    } else {
        float* cst = sh;              // [64n][128m] overlay
        const float* ps = sh + 8192;
        const float SC = 1.0507009873554805f, AL = 1.6732632423543772f;
        #pragma unroll
        for (int mp = 0; mp < 4; mp++) {
            int m0 = ((mp & 1) ? tmq * 4 + 2 : tmq * 4) + ((mp >> 1) ? 64 : 0);
            int mg0 = mBase + m0;
            float ob0 = (mg0 < M) ? bias[mg0] : 0.f;
            float ob1 = (mg0 + 1 < M) ? bias[mg0 + 1] : 0.f;
            #pragma unroll
            for (int n = 0; n < 8; n++) {
                int nn = (n < 4) ? (tnq * 4 + n) : (32 + tnq * 4 + n - 4);
                float2 c = unpk(acc[mp][n]);
                float v0 = c.x + ob0; v0 = SC * (v0 > 0.f ? v0 : AL * expm1f(v0));
                float v1 = c.y + ob1; v1 = SC * (v1 > 0.f ? v1 : AL * expm1f(v1));
                float pn = ps[nn];
                cst[nn * 128 + m0] = v0 * pn;
                cst[nn * 128 + m0 + 1] = v1 * pn;
            }
        }
        __syncthreads();
        int mrem = M - mBase; if (mrem > 128) mrem = 128;
        if (tid < mrem) {
            #pragma unroll 4
            for (int n = 0; n < 64; n++)
                out[(size_t)n * VS + mBase + tid] = cst[n * 128 + tid];
        }
    }
}

// ============ small split-K GEMM (K=512, N=64, 64-wide K chunks) ============
// grid = (M/64, SPL[, z]). outp[split*(M*64) + m*64 + b] partials.
template <bool TRANSA>
__device__ __forceinline__ void small_body(const float* __restrict__ A,
                                           const float* __restrict__ B,
                                           float* __restrict__ outp, int M)
{
    __shared__ float sA[1024], sB[1024];
    const int tid = threadIdx.x;
    const int tmq = tid & 15, tnq = tid >> 4;
    const int mBase = blockIdx.x * 64;
    const int kBase = blockIdx.y * 64;
    float acc[4][4] = {};

    for (int k0 = kBase; k0 < kBase + 64; k0 += 16) {
        __syncthreads();
        if (!TRANSA) {
            int r = tid >> 2, c4 = tid & 3;
            float4 va = *(const float4*)(A + (size_t)(mBase + r) * 512 + k0 + c4 * 4);
            sA[(c4 * 4 + 0) * 64 + r] = va.x;
            sA[(c4 * 4 + 1) * 64 + r] = va.y;
            sA[(c4 * 4 + 2) * 64 + r] = va.z;
            sA[(c4 * 4 + 3) * 64 + r] = va.w;
        } else {
            #pragma unroll
            for (int j = 0; j < 4; j++) {
                int idx = tid + 256 * j;
                int kk = idx >> 6, m = idx & 63;
                sA[kk * 64 + m] = A[(size_t)(k0 + kk) * 512 + mBase + m];
            }
        }
        {
            int r = tid >> 2, c4 = tid & 3;
            float4 vb = *(const float4*)(B + (size_t)r * 512 + k0 + c4 * 4);
            sB[(c4 * 4 + 0) * 64 + r] = vb.x;
            sB[(c4 * 4 + 1) * 64 + r] = vb.y;
            sB[(c4 * 4 + 2) * 64 + r] = vb.z;
            sB[(c4 * 4 + 3) * 64 + r] = vb.w;
        }
        __syncthreads();
        #pragma unroll
        for (int kk = 0; kk < 16; kk++) {
            float4 a = *(const float4*)&sA[kk * 64 + tmq * 4];
            float4 b = *(const float4*)&sB[kk * 64 + tnq * 4];
            float av[4] = {a.x, a.y, a.z, a.w};
            float bv[4] = {b.x, b.y, b.z, b.w};
            #pragma unroll
            for (int i = 0; i < 4; i++)
                #pragma unroll
                for (int j = 0; j < 4; j++) acc[i][j] += av[i] * bv[j];
        }
    }
    float* dst = outp + (size_t)blockIdx.y * M * 64;
    #pragma unroll
    for (int i = 0; i < 4; i++)
        #pragma unroll
        for (int j = 0; j < 4; j++)
            dst[(size_t)(mBase + tmq * 4 + i) * 64 + tnq * 4 + j] = acc[i][j];
}

template <bool TRANSA>
__global__ void __launch_bounds__(256)
small_gemm(const float* __restrict__ A, const float* __restrict__ B,
           float* __restrict__ outp, int M)
{
    small_body<TRANSA>(A, B, outp, M);
}

__global__ void __launch_bounds__(256)
small_gemm_dual(const float* __restrict__ A0, const float* __restrict__ B0,
                float* __restrict__ O0,
                const float* __restrict__ A1, const float* __restrict__ B1,
                float* __restrict__ O1, int M)
{
    if (blockIdx.z == 0) small_body<false>(A0, B0, O0, M);
    else                 small_body<false>(A1, B1, O1, M);
}

// ============ x2 partial reduce + b_attn ============
__global__ void x2red(const float* __restrict__ xp, const float* __restrict__ battn,
                      float* __restrict__ x2s)
{
    int idx = blockIdx.x * 256 + threadIdx.x;   // 32768 = 512*64
    int n = idx >> 6;
    float a = battn[n];
    #pragma unroll
    for (int s = 0; s < SPL; s++) a += xp[s * 32768 + idx];
    x2s[idx] = a;
}

// ============ GRU gates: reduce split-K partials + bias + gate math ============
__global__ void gru_gates(const float* __restrict__ gip, const float* __restrict__ ghp,
                          const float* __restrict__ b_ih, const float* __restrict__ b_hh,
                          const float* __restrict__ h0,
                          float* __restrict__ gh, float* __restrict__ gs,
                          float* __restrict__ dhid)
{
    int idx = blockIdx.x * 256 + threadIdx.x;   // 32768 = B*H
    int b = idx & 63, j = idx >> 6;
    float ir = b_ih[j], iz = b_ih[512 + j], in_ = b_ih[1024 + j];
    float hr = b_hh[j], hz = b_hh[512 + j], hn = b_hh[1024 + j];
    #pragma unroll
    for (int s = 0; s < SPL; s++) {
        const float* gi = gip + s * 98304;
        const float* gq = ghp + s * 98304;
        ir += gi[j * 64 + b];  iz += gi[(512 + j) * 64 + b];  in_ += gi[(1024 + j) * 64 + b];
        hr += gq[j * 64 + b];  hz += gq[(512 + j) * 64 + b];  hn += gq[(1024 + j) * 64 + b];
    }
    float r = 1.f / (1.f + expf(-(ir + hr)));
    float z = 1.f / (1.f + expf(-(iz + hz)));
    float n = tanhf(in_ + r * hn);
    float h = (1.f - z) * n + z * h0[b * 512 + j];
    gh[b * 512 + j] = h;
    gs[b * 1024 + j] = h;
    dhid[b * 512 + j] = h;
}

__global__ void softmax_col(const float* __restrict__ sp, float* __restrict__ attn,
                            float* __restrict__ dattn)
{
    int b = blockIdx.x, tid = threadIdx.x;
    __shared__ float sv[SS];
    __shared__ float rb[8];
    __shared__ float smax, ssum;
    float mx = -3.4e38f;
    for (int s = tid; s < SS; s += 256) {
        float xv = 0.f;
        #pragma unroll
        for (int q = 0; q < 8; q++) xv += sp[q * (SS * BB) + s * BB + b];
        sv[s] = xv;
        mx = fmaxf(mx, xv);
    }
    #pragma unroll
    for (int o = 16; o; o >>= 1) mx = fmaxf(mx, __shfl_xor_sync(0xffffffffu, mx, o));
    if ((tid & 31) == 0) rb[tid >> 5] = mx;
    __syncthreads();
    if (tid == 0) {
        float m2 = rb[0];
        #pragma unroll
        for (int i = 1; i < 8; i++) m2 = fmaxf(m2, rb[i]);
        smax = m2;
    }
    __syncthreads();
    float sum = 0.f;
    for (int s = tid; s < SS; s += 256) {
        float e = expf(sv[s] - smax);
        sv[s] = e;
        sum += e;
    }
    #pragma unroll
    for (int o = 16; o; o >>= 1) sum += __shfl_xor_sync(0xffffffffu, sum, o);
    if ((tid & 31) == 0) rb[tid >> 5] = sum;
    __syncthreads();
    if (tid == 0) {
        float t = 0.f;
        #pragma unroll
        for (int i = 0; i < 8; i++) t += rb[i];
        ssum = t;
    }
    __syncthreads();
    float inv = 1.f / ssum;
    for (int s = tid; s < SS; s += 256) {
        float a = sv[s] * inv;
        attn[s * BB + b] = a;
        dattn[s * BB + b] = a;
    }
}

__global__ void context_k(const float* __restrict__ attn, const float* __restrict__ enc,
                          float* __restrict__ gs)
{
    int b = blockIdx.x;
    int h = blockIdx.y * 128 + threadIdx.x;
    __shared__ float at[SS];
    for (int s = threadIdx.x; s < SS; s += 128) at[s] = attn[s * BB + b];
    __syncthreads();
    float acc = 0.f;
    const float* p = enc + (size_t)b * 512 + h;
    #pragma unroll 8
    for (int s = 0; s < SS; s++) acc += at[s] * p[(size_t)s * (BB * HH)];
    gs[b * 1024 + 512 + h] = acc;
}

__global__ void pgen_k(const float* __restrict__ gs, const float* __restrict__ x,
                       const float* __restrict__ pWh, const float* __restrict__ pWs,
                       const float* __restrict__ pWx, const float* __restrict__ pWx_b,
                       float* __restrict__ gp, float* __restrict__ dp)
{
    int b = blockIdx.x, tid = threadIdx.x;
    __shared__ float rb[4];
    float a = 0.f;
    for (int j = tid; j < 512; j += 128) {
        a += gs[b * 1024 + 512 + j] * pWh[j]
           + gs[b * 1024 + j] * pWs[j]
           + x[b * 512 + j] * pWx[j];
    }
    #pragma unroll
    for (int o = 16; o; o >>= 1) a += __shfl_xor_sync(0xffffffffu, a, o);
    if ((tid & 31) == 0) rb[tid >> 5] = a;
    __syncthreads();
    if (tid == 0) {
        float t = rb[0] + rb[1] + rb[2] + rb[3];
        float p = 1.f / (1.f + expf(-(t + pWx_b[0])));
        gp[b] = p; dp[b] = p;
    }
}

__global__ void oov_k(const float* __restrict__ attn, const int* __restrict__ mask,
                      const float* __restrict__ gp, float* __restrict__ dout)
{
    int idx = blockIdx.x * 256 + threadIdx.x;
    if (idx >= SS * BB) return;
    int s = idx >> 6, b = idx & 63;
    dout[(size_t)b * VS + VV + s] = (1.f - gp[b]) * attn[idx] * (float)mask[idx];
}

extern "C" void kernel_launch(void* const* d_in, const int* in_sizes, int n_in,
                              void* d_out, int out_size)
{
    const float* x      = (const float*)d_in[0];
    const float* enc    = (const float*)d_in[1];
    const int*   mask   = (const int*)d_in[2];
    const float* h0     = (const float*)d_in[3];
    const float* W_ih   = (const float*)d_in[4];
    const float* W_hh   = (const float*)d_in[5];
    const float* b_ih   = (const float*)d_in[6];
    const float* b_hh   = (const float*)d_in[7];
    const float* out_W  = (const float*)d_in[8];
    const float* out_b  = (const float*)d_in[9];
    const float* v      = (const float*)d_in[10];
    const float* Wh     = (const float*)d_in[11];
    const float* Ws     = (const float*)d_in[12];
    const float* b_attn = (const float*)d_in[13];
    const float* pWh    = (const float*)d_in[14];
    const float* pWs    = (const float*)d_in[15];
    const float* pWx    = (const float*)d_in[16];
    const float* pWx_b  = (const float*)d_in[17];
    float* out = (float*)d_out;

    float *gip, *ghp, *x2p, *x2s, *hb, *spart, *attn, *gs, *pb;
    cudaGetSymbolAddress((void**)&gip,   g_gip);
    cudaGetSymbolAddress((void**)&ghp,   g_ghp);
    cudaGetSymbolAddress((void**)&x2p,   g_x2p);
    cudaGetSymbolAddress((void**)&x2s,   g_x2s);
    cudaGetSymbolAddress((void**)&hb,    g_h);
    cudaGetSymbolAddress((void**)&spart, g_spart);
    cudaGetSymbolAddress((void**)&attn,  g_attn);
    cudaGetSymbolAddress((void**)&gs,    g_gs);
    cudaGetSymbolAddress((void**)&pb,    g_p);

    float* dout  = out;
    float* dhid  = out + (size_t)BB * VS;
    float* dp    = dhid + (size_t)BB * HH;
    float* dattn = dp + BB;

    small_gemm_dual<<<dim3(24, SPL, 2), 256>>>(W_ih, x, gip, W_hh, h0, ghp, 1536);
    gru_gates<<<128, 256>>>(gip, ghp, b_ih, b_hh, h0, hb, gs, dhid);
    small_gemm<true><<<dim3(8, SPL), 256>>>(Ws, hb, x2p, 512);
    x2red<<<128, 256>>>(x2p, b_attn, x2s);
    gemm_nt<1, true><<<dim3(200, 8), 128>>>(enc, Wh, nullptr, spart,
                                            SS * BB, 512, 512, x2s, v, nullptr);
    softmax_col<<<64, 256>>>(spart, attn, dattn);
    context_k<<<dim3(64, 4), 128>>>(attn, enc, gs);
    pgen_k<<<64, 128>>>(gs, x, pWh, pWs, pWx, pWx_b, pb, dp);
    gemm_nt<2, false><<<dim3(391, 1), 128>>>(out_W, gs, out_b, dout,
                                             VV, 2 * HH, 0, nullptr, nullptr, pb);
    oov_k<<<100, 256>>>(attn, mask, pb, dout);
}

// round 5
// speedup vs baseline: 1.1399x; 1.1399x over previous
#include <cuda_runtime.h>
#include <math.h>

#define HH 512
#define BB 64
#define SS 400
#define VV 50000
#define VS 50400
#define SPL 8

typedef unsigned long long ull;

// ---------------- scratch ----------------
__device__ __align__(16) float g_gip[SPL * 1536 * 64];
__device__ __align__(16) float g_ghp[SPL * 1536 * 64];
__device__ __align__(16) float g_x2p[SPL * 512 * 64];
__device__ __align__(16) float g_h[BB * HH];
__device__ __align__(16) float g_spart[8 * SS * BB];
__device__ __align__(16) float g_attn[SS * BB];
__device__ __align__(16) float g_gs[BB * 2 * HH];
__device__ __align__(16) float g_p[BB];

// ---------------- f32x2 helpers ----------------
__device__ __forceinline__ ull dup2(float x) {
    ull d; unsigned r = __float_as_uint(x);
    asm("mov.b64 %0, {%1,%2};" : "=l"(d) : "r"(r), "r"(r));
    return d;
}
__device__ __forceinline__ ull fma2(ull a, ull b, ull c) {
    ull d;
    asm("fma.rn.f32x2 %0, %1, %2, %3;" : "=l"(d) : "l"(a), "l"(b), "l"(c));
    return d;
}
__device__ __forceinline__ float2 unpk(ull v) {
    unsigned lo, hi;
    asm("mov.b64 {%0,%1}, %2;" : "=r"(lo), "=r"(hi) : "l"(v));
    return make_float2(__uint_as_float(lo), __uint_as_float(hi));
}

// ============ big NT GEMM, double-buffered (R3 mainloop, n-paired acc) ============
// C[m][n] = sum_k A[m][k] * B(n,k). BM=128, BN=64, BK=16, 128 threads.
// TB=false: B row-major [n][k] stride K. TB=true: B is [k][n] stride ldb.
// EPI1: out[by*25600+m] = sum_n tanh(acc + x2ps[n][b]) * v[n]  (8 partials)
// EPI2: out[n*VS+m] = p[n] * selu(acc + bias[m])
template <int EPI, bool TB>
__global__ void __launch_bounds__(128)
gemm_nt(const float* __restrict__ A, const float* __restrict__ Bm,
        const float* __restrict__ bias, float* __restrict__ out,
        int M, int K, int ldb,
        const float* __restrict__ xp, const float* __restrict__ ev,
        const float* __restrict__ ep, const float* __restrict__ battn)
{
    __shared__ float sh[11328];   // buf0[0..3072) buf1[3072..6144) extras beyond

    const int tid = threadIdx.x;
    const int tmq = tid & 15, tnq = tid >> 4;
    const int mBase = blockIdx.x * 128, nBase = blockIdx.y * 64;

    if (EPI == 1) {
        // x2ps[n][b] = sum_s x2part[s] + b_attn[n]   at sh+6144 (64x64)
        #pragma unroll
        for (int i = 0; i < 8; i++) {
            int idx4 = tid + 128 * i;
            int n = idx4 >> 4, b4 = idx4 & 15;
            float ba = battn[nBase + n];
            float4 a = make_float4(ba, ba, ba, ba);
            #pragma unroll
            for (int s = 0; s < SPL; s++) {
                float4 t = *(const float4*)(xp + (size_t)s * 32768 +
                                            (size_t)(nBase + n) * 64 + b4 * 4);
                a.x += t.x; a.y += t.y; a.z += t.z; a.w += t.w;
            }
            *(float4*)(sh + 6144 + n * 64 + b4 * 4) = a;
        }
        if (tid < 64) sh[10240 + tid] = ev[nBase + tid];
    }
    if (EPI == 2 && tid < 64) sh[8192 + tid] = ep[tid];

    ull acc[8][4];
    #pragma unroll
    for (int i = 0; i < 8; i++)
        #pragma unroll
        for (int j = 0; j < 4; j++) acc[i][j] = 0ull;

    float4 pa[4], pb[2];

    auto loadA = [&](int k0) {
        #pragma unroll
        for (int i = 0; i < 4; i++) {
            int q = tid + 128 * i, r = q >> 2, c4 = q & 3;
            int m = mBase + r;
            pa[i] = (m < M) ? *(const float4*)(A + (size_t)m * K + k0 + c4 * 4)
                            : make_float4(0.f, 0.f, 0.f, 0.f);
        }
    };
    auto loadB = [&](int k0) {
        #pragma unroll
        for (int i = 0; i < 2; i++) {
            int q = tid + 128 * i;
            if (!TB) {
                int r = q >> 2, c4 = q & 3;
                pb[i] = *(const float4*)(Bm + (size_t)(nBase + r) * K + k0 + c4 * 4);
            } else {
                int kk = q >> 4, n4 = q & 15;
                pb[i] = *(const float4*)(Bm + (size_t)(k0 + kk) * ldb + nBase + n4 * 4);
            }
        }
    };
    auto storeT = [&](float* buf) {
        float* sA = buf; float* sB = buf + 2048;
        #pragma unroll
        for (int i = 0; i < 4; i++) {
            int q = tid + 128 * i, r = q >> 2, c4 = q & 3;
            sA[(c4 * 4 + 0) * 128 + r] = pa[i].x;
            sA[(c4 * 4 + 1) * 128 + r] = pa[i].y;
            sA[(c4 * 4 + 2) * 128 + r] = pa[i].z;
            sA[(c4 * 4 + 3) * 128 + r] = pa[i].w;
        }
        #pragma unroll
        for (int i = 0; i < 2; i++) {
            int q = tid + 128 * i;
            if (!TB) {
                int r = q >> 2, c4 = q & 3;
                sB[(c4 * 4 + 0) * 64 + r] = pb[i].x;
                sB[(c4 * 4 + 1) * 64 + r] = pb[i].y;
                sB[(c4 * 4 + 2) * 64 + r] = pb[i].z;
                sB[(c4 * 4 + 3) * 64 + r] = pb[i].w;
            } else {
                int kk = q >> 4, n4 = q & 15;
                *(float4*)&sB[kk * 64 + n4 * 4] = pb[i];
            }
        }
    };

    loadA(0); loadB(0);
    storeT(sh);
    __syncthreads();

    const int T = K >> 4;
    for (int t = 0; t < T; t++) {
        float* cb = sh + (t & 1) * 3072;
        if (t + 1 < T) { loadA((t + 1) << 4); loadB((t + 1) << 4); }
        float* sA = cb; float* sB = cb + 2048;
        #pragma unroll
        for (int kk = 0; kk < 16; kk++) {
            const float4 a0 = *(const float4*)&sA[kk * 128 + tmq * 4];
            const float4 a1 = *(const float4*)&sA[kk * 128 + 64 + tmq * 4];
            ull ad[8];
            ad[0]=dup2(a0.x); ad[1]=dup2(a0.y); ad[2]=dup2(a0.z); ad[3]=dup2(a0.w);
            ad[4]=dup2(a1.x); ad[5]=dup2(a1.y); ad[6]=dup2(a1.z); ad[7]=dup2(a1.w);
            const ulonglong2 b0 = *(const ulonglong2*)&sB[kk * 64 + tnq * 4];
            const ulonglong2 b1 = *(const ulonglong2*)&sB[kk * 64 + 32 + tnq * 4];
            #pragma unroll
            for (int i = 0; i < 8; i++) {
                acc[i][0] = fma2(ad[i], b0.x, acc[i][0]);
                acc[i][1] = fma2(ad[i], b0.y, acc[i][1]);
                acc[i][2] = fma2(ad[i], b1.x, acc[i][2]);
                acc[i][3] = fma2(ad[i], b1.y, acc[i][3]);
            }
        }
        if (t + 1 < T) storeT(sh + ((t + 1) & 1) * 3072);
        __syncthreads();
    }

    if (EPI == 1) {
        float* x2ps = sh + 6144;
        float* vs = sh + 10240;
        float* red = sh + 10304;
        #pragma unroll
        for (int mi = 0; mi < 8; mi++) {
            int mloc = (mi < 4) ? (tmq * 4 + mi) : (64 + tmq * 4 + mi - 4);
            int bcol = mloc & 63;
            float s = 0.f;
            #pragma unroll
            for (int nj = 0; nj < 4; nj++) {
                int nb = (nj < 2) ? (tnq * 4 + nj * 2) : (32 + tnq * 4 + (nj - 2) * 2);
                float2 c = unpk(acc[mi][nj]);
                s += tanhf(c.x + x2ps[nb * 64 + bcol]) * vs[nb];
                s += tanhf(c.y + x2ps[(nb + 1) * 64 + bcol]) * vs[nb + 1];
            }
            red[tnq * 128 + mloc] = s;
        }
        __syncthreads();
        float t = 0.f;
        #pragma unroll
        for (int g = 0; g < 8; g++) t += red[g * 128 + tid];
        out[(size_t)blockIdx.y * (SS * BB) + mBase + tid] = t;
    } else {
        float* cst = sh;
        float* ps = sh + 8192;
        const float SC = 1.0507009873554805f, AL = 1.6732632423543772f;
        #pragma unroll
        for (int mi = 0; mi < 8; mi++) {
            int mloc = (mi < 4) ? (tmq * 4 + mi) : (64 + tmq * 4 + mi - 4);
            int m = mBase + mloc;
            float ob = (m < M) ? bias[m] : 0.f;
            #pragma unroll
            for (int nj = 0; nj < 4; nj++) {
                int nb = (nj < 2) ? (tnq * 4 + nj * 2) : (32 + tnq * 4 + (nj - 2) * 2);
                float2 c = unpk(acc[mi][nj]);
                float v0 = c.x + ob; v0 = SC * (v0 > 0.f ? v0 : AL * expm1f(v0));
                float v1 = c.y + ob; v1 = SC * (v1 > 0.f ? v1 : AL * expm1f(v1));
                cst[nb * 128 + mloc] = v0 * ps[nb];
                cst[(nb + 1) * 128 + mloc] = v1 * ps[nb + 1];
            }
        }
        __syncthreads();
        int mrem = M - mBase; if (mrem > 128) mrem = 128;
        if (tid < mrem) {
            #pragma unroll 4
            for (int n = 0; n < 64; n++)
                out[(size_t)n * VS + mBase + tid] = cst[n * 128 + tid];
        }
    }
}

// ============ small split-K GEMM (K=512, N=64, 64-wide K chunks) ============
template <bool TRANSA>
__device__ __forceinline__ void small_body(const float* __restrict__ A,
                                           const float* __restrict__ B,
                                           float* __restrict__ outp, int M)
{
    __shared__ float sA[1024], sB[1024];
    const int tid = threadIdx.x;
    const int tmq = tid & 15, tnq = tid >> 4;
    const int mBase = blockIdx.x * 64;
    const int kBase = blockIdx.y * 64;
    float acc[4][4] = {};

    for (int k0 = kBase; k0 < kBase + 64; k0 += 16) {
        __syncthreads();
        if (!TRANSA) {
            int r = tid >> 2, c4 = tid & 3;
            float4 va = *(const float4*)(A + (size_t)(mBase + r) * 512 + k0 + c4 * 4);
            sA[(c4 * 4 + 0) * 64 + r] = va.x;
            sA[(c4 * 4 + 1) * 64 + r] = va.y;
            sA[(c4 * 4 + 2) * 64 + r] = va.z;
            sA[(c4 * 4 + 3) * 64 + r] = va.w;
        } else {
            #pragma unroll
            for (int j = 0; j < 4; j++) {
                int idx = tid + 256 * j;
                int kk = idx >> 6, m = idx & 63;
                sA[kk * 64 + m] = A[(size_t)(k0 + kk) * 512 + mBase + m];
            }
        }
        {
            int r = tid >> 2, c4 = tid & 3;
            float4 vb = *(const float4*)(B + (size_t)r * 512 + k0 + c4 * 4);
            sB[(c4 * 4 + 0) * 64 + r] = vb.x;
            sB[(c4 * 4 + 1) * 64 + r] = vb.y;
            sB[(c4 * 4 + 2) * 64 + r] = vb.z;
            sB[(c4 * 4 + 3) * 64 + r] = vb.w;
        }
        __syncthreads();
        #pragma unroll
        for (int kk = 0; kk < 16; kk++) {
            float4 a = *(const float4*)&sA[kk * 64 + tmq * 4];
            float4 b = *(const float4*)&sB[kk * 64 + tnq * 4];
            float av[4] = {a.x, a.y, a.z, a.w};
            float bv[4] = {b.x, b.y, b.z, b.w};
            #pragma unroll
            for (int i = 0; i < 4; i++)
                #pragma unroll
                for (int j = 0; j < 4; j++) acc[i][j] += av[i] * bv[j];
        }
    }
    float* dst = outp + (size_t)blockIdx.y * M * 64;
    #pragma unroll
    for (int i = 0; i < 4; i++)
        #pragma unroll
        for (int j = 0; j < 4; j++)
            dst[(size_t)(mBase + tmq * 4 + i) * 64 + tnq * 4 + j] = acc[i][j];
}

template <bool TRANSA>
__global__ void __launch_bounds__(256)
small_gemm(const float* __restrict__ A, const float* __restrict__ B,
           float* __restrict__ outp, int M)
{
    small_body<TRANSA>(A, B, outp, M);
}

__global__ void __launch_bounds__(256)
small_gemm_dual(const float* __restrict__ A0, const float* __restrict__ B0,
                float* __restrict__ O0,
                const float* __restrict__ A1, const float* __restrict__ B1,
                float* __restrict__ O1, int M)
{
    if (blockIdx.z == 0) small_body<false>(A0, B0, O0, M);
    else                 small_body<false>(A1, B1, O1, M);
}

// ============ GRU gates ============
__global__ void gru_gates(const float* __restrict__ gip, const float* __restrict__ ghp,
                          const float* __restrict__ b_ih, const float* __restrict__ b_hh,
                          const float* __restrict__ h0,
                          float* __restrict__ gh, float* __restrict__ gs,
                          float* __restrict__ dhid)
{
    int idx = blockIdx.x * 256 + threadIdx.x;
    int b = idx & 63, j = idx >> 6;
    float ir = b_ih[j], iz = b_ih[512 + j], in_ = b_ih[1024 + j];
    float hr = b_hh[j], hz = b_hh[512 + j], hn = b_hh[1024 + j];
    #pragma unroll
    for (int s = 0; s < SPL; s++) {
        const float* gi = gip + s * 98304;
        const float* gq = ghp + s * 98304;
        ir += gi[j * 64 + b];  iz += gi[(512 + j) * 64 + b];  in_ += gi[(1024 + j) * 64 + b];
        hr += gq[j * 64 + b];  hz += gq[(512 + j) * 64 + b];  hn += gq[(1024 + j) * 64 + b];
    }
    float r = 1.f / (1.f + expf(-(ir + hr)));
    float z = 1.f / (1.f + expf(-(iz + hz)));
    float n = tanhf(in_ + r * hn);
    float h = (1.f - z) * n + z * h0[b * 512 + j];
    gh[b * 512 + j] = h;
    gs[b * 1024 + j] = h;
    dhid[b * 512 + j] = h;
}

__global__ void softmax_col(const float* __restrict__ sp, float* __restrict__ attn,
                            float* __restrict__ dattn)
{
    int b = blockIdx.x, tid = threadIdx.x;
    __shared__ float sv[SS];
    __shared__ float rb[8];
    __shared__ float smax, ssum;
    float mx = -3.4e38f;
    for (int s = tid; s < SS; s += 256) {
        float xv = 0.f;
        #pragma unroll
        for (int q = 0; q < 8; q++) xv += sp[q * (SS * BB) + s * BB + b];
        sv[s] = xv;
        mx = fmaxf(mx, xv);
    }
    #pragma unroll
    for (int o = 16; o; o >>= 1) mx = fmaxf(mx, __shfl_xor_sync(0xffffffffu, mx, o));
    if ((tid & 31) == 0) rb[tid >> 5] = mx;
    __syncthreads();
    if (tid == 0) {
        float m2 = rb[0];
        #pragma unroll
        for (int i = 1; i < 8; i++) m2 = fmaxf(m2, rb[i]);
        smax = m2;
    }
    __syncthreads();
    float sum = 0.f;
    for (int s = tid; s < SS; s += 256) {
        float e = expf(sv[s] - smax);
        sv[s] = e;
        sum += e;
    }
    #pragma unroll
    for (int o = 16; o; o >>= 1) sum += __shfl_xor_sync(0xffffffffu, sum, o);
    if ((tid & 31) == 0) rb[tid >> 5] = sum;
    __syncthreads();
    if (tid == 0) {
        float t = 0.f;
        #pragma unroll
        for (int i = 0; i < 8; i++) t += rb[i];
        ssum = t;
    }
    __syncthreads();
    float inv = 1.f / ssum;
    for (int s = tid; s < SS; s += 256) {
        float a = sv[s] * inv;
        attn[s * BB + b] = a;
        dattn[s * BB + b] = a;
    }
}

__global__ void context_k(const float* __restrict__ attn, const float* __restrict__ enc,
                          float* __restrict__ gs)
{
    int b = blockIdx.x;
    int h = blockIdx.y * 128 + threadIdx.x;
    __shared__ float at[SS];
    for (int s = threadIdx.x; s < SS; s += 128) at[s] = attn[s * BB + b];
    __syncthreads();
    float acc = 0.f;
    const float* p = enc + (size_t)b * 512 + h;
    #pragma unroll 8
    for (int s = 0; s < SS; s++) acc += at[s] * p[(size_t)s * (BB * HH)];
    gs[b * 1024 + 512 + h] = acc;
}

__global__ void pgen_k(const float* __restrict__ gs, const float* __restrict__ x,
                       const float* __restrict__ pWh, const float* __restrict__ pWs,
                       const float* __restrict__ pWx, const float* __restrict__ pWx_b,
                       float* __restrict__ gp, float* __restrict__ dp)
{
    int b = blockIdx.x, tid = threadIdx.x;
    __shared__ float rb[4];
    float a = 0.f;
    for (int j = tid; j < 512; j += 128) {
        a += gs[b * 1024 + 512 + j] * pWh[j]
           + gs[b * 1024 + j] * pWs[j]
           + x[b * 512 + j] * pWx[j];
    }
    #pragma unroll
    for (int o = 16; o; o >>= 1) a += __shfl_xor_sync(0xffffffffu, a, o);
    if ((tid & 31) == 0) rb[tid >> 5] = a;
    __syncthreads();
    if (tid == 0) {
        float t = rb[0] + rb[1] + rb[2] + rb[3];
        float p = 1.f / (1.f + expf(-(t + pWx_b[0])));
        gp[b] = p; dp[b] = p;
    }
}

__global__ void oov_k(const float* __restrict__ attn, const int* __restrict__ mask,
                      const float* __restrict__ gp, float* __restrict__ dout)
{
    int idx = blockIdx.x * 256 + threadIdx.x;
    if (idx >= SS * BB) return;
    int s = idx >> 6, b = idx & 63;
    dout[(size_t)b * VS + VV + s] = (1.f - gp[b]) * attn[idx] * (float)mask[idx];
}

extern "C" void kernel_launch(void* const* d_in, const int* in_sizes, int n_in,
                              void* d_out, int out_size)
{
    const float* x      = (const float*)d_in[0];
    const float* enc    = (const float*)d_in[1];
    const int*   mask   = (const int*)d_in[2];
    const float* h0     = (const float*)d_in[3];
    const float* W_ih   = (const float*)d_in[4];
    const float* W_hh   = (const float*)d_in[5];
    const float* b_ih   = (const float*)d_in[6];
    const float* b_hh   = (const float*)d_in[7];
    const float* out_W  = (const float*)d_in[8];
    const float* out_b  = (const float*)d_in[9];
    const float* v      = (const float*)d_in[10];
    const float* Wh     = (const float*)d_in[11];
    const float* Ws     = (const float*)d_in[12];
    const float* b_attn = (const float*)d_in[13];
    const float* pWh    = (const float*)d_in[14];
    const float* pWs    = (const float*)d_in[15];
    const float* pWx    = (const float*)d_in[16];
    const float* pWx_b  = (const float*)d_in[17];
    float* out = (float*)d_out;

    float *gip, *ghp, *x2p, *hb, *spart, *attn, *gs, *pb;
    cudaGetSymbolAddress((void**)&gip,   g_gip);
    cudaGetSymbolAddress((void**)&ghp,   g_ghp);
    cudaGetSymbolAddress((void**)&x2p,   g_x2p);
    cudaGetSymbolAddress((void**)&hb,    g_h);
    cudaGetSymbolAddress((void**)&spart, g_spart);
    cudaGetSymbolAddress((void**)&attn,  g_attn);
    cudaGetSymbolAddress((void**)&gs,    g_gs);
    cudaGetSymbolAddress((void**)&pb,    g_p);

    float* dout  = out;
    float* dhid  = out + (size_t)BB * VS;
    float* dp    = dhid + (size_t)BB * HH;
    float* dattn = dp + BB;

    // launch index 3 = score GEMM (profiler captures idx 3)
    small_gemm_dual<<<dim3(24, SPL, 2), 256>>>(W_ih, x, gip, W_hh, h0, ghp, 1536); // 0
    gru_gates<<<128, 256>>>(gip, ghp, b_ih, b_hh, h0, hb, gs, dhid);               // 1
    small_gemm<true><<<dim3(8, SPL), 256>>>(Ws, hb, x2p, 512);                     // 2
    gemm_nt<1, true><<<dim3(200, 8), 128>>>(enc, Wh, nullptr, spart,               // 3
                                            SS * BB, 512, 512, x2p, v, nullptr, b_attn);
    softmax_col<<<64, 256>>>(spart, attn, dattn);                                  // 4
    context_k<<<dim3(64, 4), 128>>>(attn, enc, gs);                                // 5
    pgen_k<<<64, 128>>>(gs, x, pWh, pWs, pWx, pWx_b, pb, dp);                      // 6
    gemm_nt<2, false><<<dim3(391, 1), 128>>>(out_W, gs, out_b, dout,               // 7
                                             VV, 2 * HH, 0, nullptr, nullptr, pb, nullptr);
    oov_k<<<100, 256>>>(attn, mask, pb, dout);                                     // 8
}

// round 7
// speedup vs baseline: 1.4751x; 1.2940x over previous
#include <cuda_runtime.h>
#include <cuda_bf16.h>
#include <mma.h>
#include <math.h>
#include <stdint.h>

using namespace nvcuda;

#define HH 512
#define BB 64
#define SS 400
#define VV 50000
#define VS 50400
#define SPL 8
#define SPLW 2

// ---------------- scratch ----------------
__device__ __align__(16) float g_gip[SPL * 1536 * 64];
__device__ __align__(16) float g_ghp[SPL * 1536 * 64];
__device__ __align__(16) float g_x2p[SPLW * 512 * 64];
__device__ __align__(16) float g_h[BB * HH];
__device__ __align__(16) float g_spart[8 * SS * BB];
__device__ __align__(16) float g_attn[SS * BB];
__device__ __align__(16) float g_gs[BB * 2 * HH];
__device__ __align__(16) float g_p[BB];
__device__ __align__(16) __nv_bfloat16 g_whh[512 * 512];   // Wh hi, [k][n]
__device__ __align__(16) __nv_bfloat16 g_whl[512 * 512];   // Wh lo, [k][n]
__device__ __align__(16) __nv_bfloat16 g_gsh[64 * 1024];   // gs hi, [b][k]
__device__ __align__(16) __nv_bfloat16 g_gsl[64 * 1024];   // gs lo, [b][k]

__device__ __forceinline__ uint32_t pack_bf2(__nv_bfloat16 a, __nv_bfloat16 b) {
    return ((uint32_t)*(uint16_t*)&b << 16) | (uint32_t)*(uint16_t*)&a;
}

// =============== score GEMM: wmma bf16 3-term split =====================
// C = enc[25600,512] @ Wh[512,512]; tile M=128 (bx), N=64 (by), Kchunk=32.
// Epilogue: spart[by*25600+m] = sum_n tanh(C + x2 + b_attn) * v[n].
// smem buffer: Ah[128][48] Al[128][48] Bh[32][80] Bl[32][80]  (bf16)
#define S_AH 0
#define S_AL 12288
#define S_BH 24576
#define S_BL 29696
#define S_BUF 34816
#define S_SMEM (2 * S_BUF)

__global__ void __launch_bounds__(256)
score_wmma(const float* __restrict__ enc,
           const __nv_bfloat16* __restrict__ whh, const __nv_bfloat16* __restrict__ whl,
           const float* __restrict__ x2p, const float* __restrict__ v,
           const float* __restrict__ battn, float* __restrict__ outp)
{
    extern __shared__ __align__(128) char sm[];
    const int tid = threadIdx.x, wid = tid >> 5;
    const int wm = wid & 3, wn = wid >> 2;           // warp grid 4(m) x 2(n)
    const int mBase = blockIdx.x * 128, nBase = blockIdx.y * 64;

    wmma::fragment<wmma::accumulator, 16, 16, 16, float> acc[2][2];
    #pragma unroll
    for (int i = 0; i < 2; i++)
        #pragma unroll
        for (int j = 0; j < 2; j++) wmma::fill_fragment(acc[i][j], 0.f);

    float4 pa[4];
    uint4 qbh, qbl;
    auto loadG = [&](int k0) {
        #pragma unroll
        for (int i = 0; i < 4; i++) {
            int q = tid + 256 * i, r = q >> 3, c4 = q & 7;
            pa[i] = *(const float4*)(enc + (size_t)(mBase + r) * 512 + k0 + c4 * 4);
        }
        int k = tid >> 3, u = tid & 7;
        qbh = *(const uint4*)(whh + (size_t)(k0 + k) * 512 + nBase + u * 8);
        qbl = *(const uint4*)(whl + (size_t)(k0 + k) * 512 + nBase + u * 8);
    };
    auto storeT = [&](char* buf) {
        #pragma unroll
        for (int i = 0; i < 4; i++) {
            int q = tid + 256 * i, r = q >> 3, c4 = q & 7;
            float x0 = pa[i].x, x1 = pa[i].y, x2 = pa[i].z, x3 = pa[i].w;
            __nv_bfloat16 h0 = __float2bfloat16_rn(x0), h1 = __float2bfloat16_rn(x1);
            __nv_bfloat16 h2 = __float2bfloat16_rn(x2), h3 = __float2bfloat16_rn(x3);
            __nv_bfloat16 l0 = __float2bfloat16_rn(x0 - __bfloat162float(h0));
            __nv_bfloat16 l1 = __float2bfloat16_rn(x1 - __bfloat162float(h1));
            __nv_bfloat16 l2 = __float2bfloat16_rn(x2 - __bfloat162float(h2));
            __nv_bfloat16 l3 = __float2bfloat16_rn(x3 - __bfloat162float(h3));
            int boff = r * 96 + c4 * 8;
            *(uint2*)(buf + S_AH + boff) = make_uint2(pack_bf2(h0, h1), pack_bf2(h2, h3));
            *(uint2*)(buf + S_AL + boff) = make_uint2(pack_bf2(l0, l1), pack_bf2(l2, l3));
        }
        int k = tid >> 3, u = tid & 7;
        *(uint4*)(buf + S_BH + k * 160 + u * 16) = qbh;
        *(uint4*)(buf + S_BL + k * 160 + u * 16) = qbl;
    };

    loadG(0);
    storeT(sm);
    __syncthreads();

    const int T = 16;            // 512 / 32
    for (int t = 0; t < T; t++) {
        char* cb = sm + (t & 1) * S_BUF;
        if (t + 1 < T) loadG((t + 1) * 32);
        const __nv_bfloat16* Ah = (const __nv_bfloat16*)(cb + S_AH);
        const __nv_bfloat16* Al = (const __nv_bfloat16*)(cb + S_AL);
        const __nv_bfloat16* Bh = (const __nv_bfloat16*)(cb + S_BH);
        const __nv_bfloat16* Bl = (const __nv_bfloat16*)(cb + S_BL);
        #pragma unroll
        for (int ks = 0; ks < 2; ks++) {
            wmma::fragment<wmma::matrix_a, 16, 16, 16, __nv_bfloat16, wmma::row_major> ah[2], al[2];
            wmma::fragment<wmma::matrix_b, 16, 16, 16, __nv_bfloat16, wmma::row_major> bh[2], bl[2];
            #pragma unroll
            for (int i = 0; i < 2; i++) {
                wmma::load_matrix_sync(ah[i], Ah + (wm * 32 + i * 16) * 48 + ks * 16, 48);
                wmma::load_matrix_sync(al[i], Al + (wm * 32 + i * 16) * 48 + ks * 16, 48);
            }
            #pragma unroll
            for (int j = 0; j < 2; j++) {
                wmma::load_matrix_sync(bh[j], Bh + ks * 16 * 80 + wn * 32 + j * 16, 80);
                wmma::load_matrix_sync(bl[j], Bl + ks * 16 * 80 + wn * 32 + j * 16, 80);
            }
            #pragma unroll
            for (int i = 0; i < 2; i++)
                #pragma unroll
                for (int j = 0; j < 2; j++) {
                    wmma::mma_sync(acc[i][j], ah[i], bh[j], acc[i][j]);
                    wmma::mma_sync(acc[i][j], ah[i], bl[j], acc[i][j]);
                    wmma::mma_sync(acc[i][j], al[i], bh[j], acc[i][j]);
                }
        }
        if (t + 1 < T) storeT(sm + ((t + 1) & 1) * S_BUF);
        __syncthreads();
    }

    // epilogue overlay: Cf[128][72] f32 @0, x2t[64][64] @36864, vv[64] @53248
    float* Cf  = (float*)sm;
    float* x2t = (float*)(sm + 36864);
    float* vv  = (float*)(sm + 53248);
    #pragma unroll
    for (int i = 0; i < 2; i++)
        #pragma unroll
        for (int j = 0; j < 2; j++)
            wmma::store_matrix_sync(Cf + (wm * 32 + i * 16) * 72 + wn * 32 + j * 16,
                                    acc[i][j], 72, wmma::mem_row_major);
    #pragma unroll
    for (int i = 0; i < 4; i++) {
        int q = tid + 256 * i, n = q >> 4, b4 = q & 15;
        float4 a = *(const float4*)(x2p + (size_t)(nBase + n) * 64 + b4 * 4);
        float4 b = *(const float4*)(x2p + 32768 + (size_t)(nBase + n) * 64 + b4 * 4);
        float ba = battn[nBase + n];
        a.x += b.x + ba; a.y += b.y + ba; a.z += b.z + ba; a.w += b.w + ba;
        *(float4*)(x2t + n * 64 + b4 * 4) = a;
    }
    if (tid < 64) vv[tid] = v[nBase + tid];
    __syncthreads();

    int m = tid >> 1, half = tid & 1, bcol = m & 63;
    float s = 0.f;
    int n0 = half * 32;
    #pragma unroll 8
    for (int n = n0; n < n0 + 32; n++)
        s += tanhf(Cf[m * 72 + n] + x2t[n * 64 + bcol]) * vv[n];
    s += __shfl_xor_sync(0xffffffffu, s, 1);
    if (!half) outp[(size_t)blockIdx.y * (SS * BB) + mBase + m] = s;
}

// =============== vocab GEMM: wmma bf16 3-term split =====================
// C[v, b] = out_W[v,1024] @ gs[b,1024]^T; tile M=128, N=64, Kchunk=32.
// EPI: out[b*VS + v] = p[b] * selu(C + out_b[v]).
#define V_AH 0
#define V_AL 12288
#define V_BH 24576
#define V_BL 30720
#define V_BUF 36864
#define V_SMEM (2 * V_BUF)

__global__ void __launch_bounds__(256)
vocab_wmma(const float* __restrict__ outW,
           const __nv_bfloat16* __restrict__ gsh, const __nv_bfloat16* __restrict__ gsl,
           const float* __restrict__ outb, const float* __restrict__ ep,
           float* __restrict__ out)
{
    extern __shared__ __align__(128) char sm[];
    const int tid = threadIdx.x, wid = tid >> 5;
    const int wm = wid & 3, wn = wid >> 2;
    const int mBase = blockIdx.x * 128;

    wmma::fragment<wmma::accumulator, 16, 16, 16, float> acc[2][2];
    #pragma unroll
    for (int i = 0; i < 2; i++)
        #pragma unroll
        for (int j = 0; j < 2; j++) wmma::fill_fragment(acc[i][j], 0.f);

    float4 pa[4];
    uint4 qbh, qbl;
    auto loadG = [&](int k0) {
        #pragma unroll
        for (int i = 0; i < 4; i++) {
            int q = tid + 256 * i, r = q >> 3, c4 = q & 7;
            int mg = mBase + r;
            pa[i] = (mg < VV) ? *(const float4*)(outW + (size_t)mg * 1024 + k0 + c4 * 4)
                              : make_float4(0.f, 0.f, 0.f, 0.f);
        }
        int n = tid >> 2, u = tid & 3;
        qbh = *(const uint4*)(gsh + (size_t)n * 1024 + k0 + u * 8);
        qbl = *(const uint4*)(gsl + (size_t)n * 1024 + k0 + u * 8);
    };
    auto storeT = [&](char* buf) {
        #pragma unroll
        for (int i = 0; i < 4; i++) {
            int q = tid + 256 * i, r = q >> 3, c4 = q & 7;
            float x0 = pa[i].x, x1 = pa[i].y, x2 = pa[i].z, x3 = pa[i].w;
            __nv_bfloat16 h0 = __float2bfloat16_rn(x0), h1 = __float2bfloat16_rn(x1);
            __nv_bfloat16 h2 = __float2bfloat16_rn(x2), h3 = __float2bfloat16_rn(x3);
            __nv_bfloat16 l0 = __float2bfloat16_rn(x0 - __bfloat162float(h0));
            __nv_bfloat16 l1 = __float2bfloat16_rn(x1 - __bfloat162float(h1));
            __nv_bfloat16 l2 = __float2bfloat16_rn(x2 - __bfloat162float(h2));
            __nv_bfloat16 l3 = __float2bfloat16_rn(x3 - __bfloat162float(h3));
            int boff = r * 96 + c4 * 8;
            *(uint2*)(buf + V_AH + boff) = make_uint2(pack_bf2(h0, h1), pack_bf2(h2, h3));
            *(uint2*)(buf + V_AL + boff) = make_uint2(pack_bf2(l0, l1), pack_bf2(l2, l3));
        }
        int n = tid >> 2, u = tid & 3;
        *(uint4*)(buf + V_BH + n * 96 + u * 16) = qbh;
        *(uint4*)(buf + V_BL + n * 96 + u * 16) = qbl;
    };

    loadG(0);
    storeT(sm);
    __syncthreads();

    const int T = 32;            // 1024 / 32
    for (int t = 0; t < T; t++) {
        char* cb = sm + (t & 1) * V_BUF;
        if (t + 1 < T) loadG((t + 1) * 32);
        const __nv_bfloat16* Ah = (const __nv_bfloat16*)(cb + V_AH);
        const __nv_bfloat16* Al = (const __nv_bfloat16*)(cb + V_AL);
        const __nv_bfloat16* Bh = (const __nv_bfloat16*)(cb + V_BH);
        const __nv_bfloat16* Bl = (const __nv_bfloat16*)(cb + V_BL);
        #pragma unroll
        for (int ks = 0; ks < 2; ks++) {
            wmma::fragment<wmma::matrix_a, 16, 16, 16, __nv_bfloat16, wmma::row_major> ah[2], al[2];
            wmma::fragment<wmma::matrix_b, 16, 16, 16, __nv_bfloat16, wmma::col_major> bh[2], bl[2];
            #pragma unroll
            for (int i = 0; i < 2; i++) {
                wmma::load_matrix_sync(ah[i], Ah + (wm * 32 + i * 16) * 48 + ks * 16, 48);
                wmma::load_matrix_sync(al[i], Al + (wm * 32 + i * 16) * 48 + ks * 16, 48);
            }
            #pragma unroll
            for (int j = 0; j < 2; j++) {
                wmma::load_matrix_sync(bh[j], Bh + (wn * 32 + j * 16) * 48 + ks * 16, 48);
                wmma::load_matrix_sync(bl[j], Bl + (wn * 32 + j * 16) * 48 + ks * 16, 48);
            }
            #pragma unroll
            for (int i = 0; i < 2; i++)
                #pragma unroll
                for (int j = 0; j < 2; j++) {
                    wmma::mma_sync(acc[i][j], ah[i], bh[j], acc[i][j]);
                    wmma::mma_sync(acc[i][j], ah[i], bl[j], acc[i][j]);
                    wmma::mma_sync(acc[i][j], al[i], bh[j], acc[i][j]);
                }
        }
        if (t + 1 < T) storeT(sm + ((t + 1) & 1) * V_BUF);
        __syncthreads();
    }

    // epilogue overlay: Cf[n 0..63][ld 132] col-ordered f32 @0, ps[64] @33792
    float* Cf = (float*)sm;
    float* ps = (float*)(sm + 33792);
    #pragma unroll
    for (int i = 0; i < 2; i++)
        #pragma unroll
        for (int j = 0; j < 2; j++)
            wmma::store_matrix_sync(Cf + (size_t)(wn * 32 + j * 16) * 132 + wm * 32 + i * 16,
                                    acc[i][j], 132, wmma::mem_col_major);
    if (tid < 64) ps[tid] = ep[tid];
    __syncthreads();

    if (tid < 128) {
        int mg = mBase + tid;
        if (mg < VV) {
            const float SC = 1.0507009873554805f, AL2 = 1.6732632423543772f;
            float ob = outb[mg];
            #pragma unroll 4
            for (int n = 0; n < 64; n++) {
                float vv2 = Cf[n * 132 + tid] + ob;
                vv2 = SC * (vv2 > 0.f ? vv2 : AL2 * expm1f(vv2));
                out[(size_t)n * VS + mg] = vv2 * ps[n];
            }
        }
    }
}

// ============ small split-K GEMM ============
template <bool TRANSA>
__device__ __forceinline__ void small_body(const float* __restrict__ A,
                                           const float* __restrict__ B,
                                           float* __restrict__ outp, int M, int kch)
{
    __shared__ float sA[1024], sB[1024];
    const int tid = threadIdx.x;
    const int tmq = tid & 15, tnq = tid >> 4;
    const int mBase = blockIdx.x * 64;
    const int kBase = blockIdx.y * kch;
    float acc[4][4] = {};

    for (int k0 = kBase; k0 < kBase + kch; k0 += 16) {
        __syncthreads();
        if (!TRANSA) {
            int r = tid >> 2, c4 = tid & 3;
            float4 va = *(const float4*)(A + (size_t)(mBase + r) * 512 + k0 + c4 * 4);
            sA[(c4 * 4 + 0) * 64 + r] = va.x;
            sA[(c4 * 4 + 1) * 64 + r] = va.y;
            sA[(c4 * 4 + 2) * 64 + r] = va.z;
            sA[(c4 * 4 + 3) * 64 + r] = va.w;
        } else {
            #pragma unroll
            for (int j = 0; j < 4; j++) {
                int idx = tid + 256 * j;
                int kk = idx >> 6, m = idx & 63;
                sA[kk * 64 + m] = A[(size_t)(k0 + kk) * 512 + mBase + m];
            }
        }
        {
            int r = tid >> 2, c4 = tid & 3;
            float4 vb = *(const float4*)(B + (size_t)r * 512 + k0 + c4 * 4);
            sB[(c4 * 4 + 0) * 64 + r] = vb.x;
            sB[(c4 * 4 + 1) * 64 + r] = vb.y;
            sB[(c4 * 4 + 2) * 64 + r] = vb.z;
            sB[(c4 * 4 + 3) * 64 + r] = vb.w;
        }
        __syncthreads();
        #pragma unroll
        for (int kk = 0; kk < 16; kk++) {
            float4 a = *(const float4*)&sA[kk * 64 + tmq * 4];
            float4 b = *(const float4*)&sB[kk * 64 + tnq * 4];
            float av[4] = {a.x, a.y, a.z, a.w};
            float bv[4] = {b.x, b.y, b.z, b.w};
            #pragma unroll
            for (int i = 0; i < 4; i++)
                #pragma unroll
                for (int j = 0; j < 4; j++) acc[i][j] += av[i] * bv[j];
        }
    }
    float* dst = outp + (size_t)blockIdx.y * M * 64;
    #pragma unroll
    for (int i = 0; i < 4; i++)
        #pragma unroll
        for (int j = 0; j < 4; j++)
            dst[(size_t)(mBase + tmq * 4 + i) * 64 + tnq * 4 + j] = acc[i][j];
}

template <bool TRANSA>
__global__ void __launch_bounds__(256)
small_gemm(const float* __restrict__ A, const float* __restrict__ B,
           float* __restrict__ outp, int M, int kch)
{
    small_body<TRANSA>(A, B, outp, M, kch);
}

// z=0: W_ih gemm, z=1: W_hh gemm, z=2: Wh -> bf16 hi/lo ([k][n], no transpose)
__global__ void __launch_bounds__(256)
small_gemm_dual(const float* __restrict__ A0, const float* __restrict__ B0,
                float* __restrict__ O0,
                const float* __restrict__ A1, const float* __restrict__ B1,
                float* __restrict__ O1, int M,
                const float* __restrict__ Wh,
                __nv_bfloat16* __restrict__ whh, __nv_bfloat16* __restrict__ whl)
{
    if (blockIdx.z == 0) { small_body<false>(A0, B0, O0, M, 64); return; }
    if (blockIdx.z == 1) { small_body<false>(A1, B1, O1, M, 64); return; }
    int bid = blockIdx.y * 24 + blockIdx.x;
    for (int idx = bid * 256 + threadIdx.x; idx < 512 * 512; idx += 192 * 256) {
        float w = Wh[idx];
        __nv_bfloat16 h = __float2bfloat16_rn(w);
        whh[idx] = h;
        whl[idx] = __float2bfloat16_rn(w - __bfloat162float(h));
    }
}

// ============ gs -> bf16 hi/lo ============
__global__ void gsconv(const float* __restrict__ gs,
                       __nv_bfloat16* __restrict__ gsh, __nv_bfloat16* __restrict__ gsl)
{
    int idx = blockIdx.x * 256 + threadIdx.x;   // 65536
    float w = gs[idx];
    __nv_bfloat16 h = __float2bfloat16_rn(w);
    gsh[idx] = h;
    gsl[idx] = __float2bfloat16_rn(w - __bfloat162float(h));
}

// ============ GRU gates ============
__global__ void gru_gates(const float* __restrict__ gip, const float* __restrict__ ghp,
                          const float* __restrict__ b_ih, const float* __restrict__ b_hh,
                          const float* __restrict__ h0,
                          float* __restrict__ gh, float* __restrict__ gs,
                          float* __restrict__ dhid)
{
    int idx = blockIdx.x * 256 + threadIdx.x;
    int b = idx & 63, j = idx >> 6;
    float ir = b_ih[j], iz = b_ih[512 + j], in_ = b_ih[1024 + j];
    float hr = b_hh[j], hz = b_hh[512 + j], hn = b_hh[1024 + j];
    #pragma unroll
    for (int s = 0; s < SPL; s++) {
        const float* gi = gip + s * 98304;
        const float* gq = ghp + s * 98304;
        ir += gi[j * 64 + b];  iz += gi[(512 + j) * 64 + b];  in_ += gi[(1024 + j) * 64 + b];
        hr += gq[j * 64 + b];  hz += gq[(512 + j) * 64 + b];  hn += gq[(1024 + j) * 64 + b];
    }
    float r = 1.f / (1.f + expf(-(ir + hr)));
    float z = 1.f / (1.f + expf(-(iz + hz)));
    float n = tanhf(in_ + r * hn);
    float h = (1.f - z) * n + z * h0[b * 512 + j];
    gh[b * 512 + j] = h;
    gs[b * 1024 + j] = h;
    dhid[b * 512 + j] = h;
}

__global__ void softmax_col(const float* __restrict__ sp, float* __restrict__ attn,
                            float* __restrict__ dattn)
{
    int b = blockIdx.x, tid = threadIdx.x;
    __shared__ float sv[SS];
    __shared__ float rb[8];
    __shared__ float smax, ssum;
    float mx = -3.4e38f;
    for (int s = tid; s < SS; s += 256) {
        float xv = 0.f;
        #pragma unroll
        for (int q = 0; q < 8; q++) xv += sp[q * (SS * BB) + s * BB + b];
        sv[s] = xv;
        mx = fmaxf(mx, xv);
    }
    #pragma unroll
    for (int o = 16; o; o >>= 1) mx = fmaxf(mx, __shfl_xor_sync(0xffffffffu, mx, o));
    if ((tid & 31) == 0) rb[tid >> 5] = mx;
    __syncthreads();
    if (tid == 0) {
        float m2 = rb[0];
        #pragma unroll
        for (int i = 1; i < 8; i++) m2 = fmaxf(m2, rb[i]);
        smax = m2;
    }
    __syncthreads();
    float sum = 0.f;
    for (int s = tid; s < SS; s += 256) {
        float e = expf(sv[s] - smax);
        sv[s] = e;
        sum += e;
    }
    #pragma unroll
    for (int o = 16; o; o >>= 1) sum += __shfl_xor_sync(0xffffffffu, sum, o);
    if ((tid & 31) == 0) rb[tid >> 5] = sum;
    __syncthreads();
    if (tid == 0) {
        float t = 0.f;
        #pragma unroll
        for (int i = 0; i < 8; i++) t += rb[i];
        ssum = t;
    }
    __syncthreads();
    float inv = 1.f / ssum;
    for (int s = tid; s < SS; s += 256) {
        float a = sv[s] * inv;
        attn[s * BB + b] = a;
        dattn[s * BB + b] = a;
    }
}

__global__ void context_k(const float* __restrict__ attn, const float* __restrict__ enc,
                          float* __restrict__ gs)
{
    int b = blockIdx.x;
    int h = blockIdx.y * 128 + threadIdx.x;
    __shared__ float at[SS];
    for (int s = threadIdx.x; s < SS; s += 128) at[s] = attn[s * BB + b];
    __syncthreads();
    float acc = 0.f;
    const float* p = enc + (size_t)b * 512 + h;
    #pragma unroll 8
    for (int s = 0; s < SS; s++) acc += at[s] * p[(size_t)s * (BB * HH)];
    gs[b * 1024 + 512 + h] = acc;
}

__global__ void pgen_k(const float* __restrict__ gs, const float* __restrict__ x,
                       const float* __restrict__ pWh, const float* __restrict__ pWs,
                       const float* __restrict__ pWx, const float* __restrict__ pWx_b,
                       float* __restrict__ gp, float* __restrict__ dp)
{
    int b = blockIdx.x, tid = threadIdx.x;
    __shared__ float rb[4];
    float a = 0.f;
    for (int j = tid; j < 512; j += 128) {
        a += gs[b * 1024 + 512 + j] * pWh[j]
           + gs[b * 1024 + j] * pWs[j]
           + x[b * 512 + j] * pWx[j];
    }
    #pragma unroll
    for (int o = 16; o; o >>= 1) a += __shfl_xor_sync(0xffffffffu, a, o);
    if ((tid & 31) == 0) rb[tid >> 5] = a;
    __syncthreads();
    if (tid == 0) {
        float t = rb[0] + rb[1] + rb[2] + rb[3];
        float p = 1.f / (1.f + expf(-(t + pWx_b[0])));
        gp[b] = p; dp[b] = p;
    }
}

__global__ void oov_k(const float* __restrict__ attn, const int* __restrict__ mask,
                      const float* __restrict__ gp, float* __restrict__ dout)
{
    int idx = blockIdx.x * 256 + threadIdx.x;
    if (idx >= SS * BB) return;
    int s = idx >> 6, b = idx & 63;
    dout[(size_t)b * VS + VV + s] = (1.f - gp[b]) * attn[idx] * (float)mask[idx];
}

extern "C" void kernel_launch(void* const* d_in, const int* in_sizes, int n_in,
                              void* d_out, int out_size)
{
    const float* x      = (const float*)d_in[0];
    const float* enc    = (const float*)d_in[1];
    const int*   mask   = (const int*)d_in[2];
    const float* h0     = (const float*)d_in[3];
    const float* W_ih   = (const float*)d_in[4];
    const float* W_hh   = (const float*)d_in[5];
    const float* b_ih   = (const float*)d_in[6];
    const float* b_hh   = (const float*)d_in[7];
    const float* out_W  = (const float*)d_in[8];
    const float* out_b  = (const float*)d_in[9];
    const float* v      = (const float*)d_in[10];
    const float* Wh     = (const float*)d_in[11];
    const float* Ws     = (const float*)d_in[12];
    const float* b_attn = (const float*)d_in[13];
    const float* pWh    = (const float*)d_in[14];
    const float* pWs    = (const float*)d_in[15];
    const float* pWx    = (const float*)d_in[16];
    const float* pWx_b  = (const float*)d_in[17];
    float* out = (float*)d_out;

    float *gip, *ghp, *x2p, *hb, *spart, *attn, *gs, *pb;
    __nv_bfloat16 *whh, *whl, *gsh, *gsl;
    cudaGetSymbolAddress((void**)&gip,   g_gip);
    cudaGetSymbolAddress((void**)&ghp,   g_ghp);
    cudaGetSymbolAddress((void**)&x2p,   g_x2p);
    cudaGetSymbolAddress((void**)&hb,    g_h);
    cudaGetSymbolAddress((void**)&spart, g_spart);
    cudaGetSymbolAddress((void**)&attn,  g_attn);
    cudaGetSymbolAddress((void**)&gs,    g_gs);
    cudaGetSymbolAddress((void**)&pb,    g_p);
    cudaGetSymbolAddress((void**)&whh,   g_whh);
    cudaGetSymbolAddress((void**)&whl,   g_whl);
    cudaGetSymbolAddress((void**)&gsh,   g_gsh);
    cudaGetSymbolAddress((void**)&gsl,   g_gsl);

    float* dout  = out;
    float* dhid  = out + (size_t)BB * VS;
    float* dp    = dhid + (size_t)BB * HH;
    float* dattn = dp + BB;

    cudaFuncSetAttribute(score_wmma, cudaFuncAttributeMaxDynamicSharedMemorySize, S_SMEM);
    cudaFuncSetAttribute(vocab_wmma, cudaFuncAttributeMaxDynamicSharedMemorySize, V_SMEM);

    small_gemm_dual<<<dim3(24, SPL, 3), 256>>>(W_ih, x, gip, W_hh, h0, ghp, 1536,
                                               Wh, whh, whl);                    // 0
    gru_gates<<<128, 256>>>(gip, ghp, b_ih, b_hh, h0, hb, gs, dhid);             // 1
    small_gemm<true><<<dim3(8, SPLW), 256>>>(Ws, hb, x2p, 512, 512 / SPLW);      // 2
    score_wmma<<<dim3(200, 8), 256, S_SMEM>>>(enc, whh, whl, x2p, v,             // 3
                                              b_attn, spart);
    softmax_col<<<64, 256>>>(spart, attn, dattn);                                // 4
    context_k<<<dim3(64, 4), 128>>>(attn, enc, gs);                              // 5
    pgen_k<<<64, 128>>>(gs, x, pWh, pWs, pWx, pWx_b, pb, dp);                    // 6
    gsconv<<<256, 256>>>(gs, gsh, gsl);                                          // 7
    vocab_wmma<<<391, 256, V_SMEM>>>(out_W, gsh, gsl, out_b, pb, dout);          // 8
    oov_k<<<100, 256>>>(attn, mask, pb, dout);                                   // 9
}